// round 13
// baseline (speedup 1.0000x reference)
#include <cuda_runtime.h>
#include <cuda_bf16.h>

#define D 128
#define MAXN 100000
#define MAXE 1600000
#define XS 129   // ull row stride; 129 ≡ 1 mod 16 → stride-1-row lanes land 2 banks apart

typedef unsigned long long ull;
typedef unsigned int uint;

// ---------------- device scratch (no allocations allowed) ----------------
__device__ int   g_cnt[MAXN];
__device__ int   g_rowptr[MAXN + 1];
__device__ int   g_cursor[MAXN];
__device__ int   g_csr[MAXE];
__device__ float g_dinv[MAXN];
__device__ int   g_bsum[128];
__device__ int   g_boff[128];
__device__ float g_h[(size_t)MAXN * D];          // dense output, fp32 (self/residual)
__device__ uint  g_hb[(size_t)MAXN * (D / 2)];   // dense output, packed bf16x2 (gathers)
__device__ float g_x[(size_t)MAXN * D];          // layer-1 activation

// ---------------- packed f32x2 helpers ----------------
__device__ __forceinline__ ull pack2(float x, float y) {
    ull r;
    asm("mov.b64 %0, {%1, %2};" : "=l"(r) : "f"(x), "f"(y));
    return r;
}
__device__ __forceinline__ void unpack2(ull v, float& x, float& y) {
    asm("mov.b64 {%0, %1}, %2;" : "=f"(x), "=f"(y) : "l"(v));
}
__device__ __forceinline__ void ffma2(ull& acc, ull a, ull b) {
    asm("fma.rn.f32x2 %0, %1, %2, %0;" : "+l"(acc) : "l"(a), "l"(b));
}
__device__ __forceinline__ void bf2x(uint v, float& lo, float& hi) {
    lo = __uint_as_float(v << 16);
    hi = __uint_as_float(v & 0xffff0000u);
}
__device__ __forceinline__ void lds_v2u64(ull& a, ull& b, const void* p) {
    asm volatile("ld.shared.v2.u64 {%0, %1}, [%2];" : "=l"(a), "=l"(b) : "l"(__cvta_generic_to_shared(p)));
}
__device__ __forceinline__ ull lds_u64(const void* p) {
    ull a;
    asm volatile("ld.shared.u64 %0, [%1];" : "=l"(a) : "l"(__cvta_generic_to_shared(p)));
    return a;
}

// ---------------- CSR build ----------------
__global__ void zero_cnt_k(int n) {
    int i = blockIdx.x * blockDim.x + threadIdx.x;
    if (i < n) g_cnt[i] = 0;
}

__global__ void count_k(const int* __restrict__ dst, int E) {
    int i = blockIdx.x * blockDim.x + threadIdx.x;
    if (i < E) atomicAdd(&g_cnt[dst[i]], 1);
}

__global__ void scan1_k(int n) {
    __shared__ int wsum[8];
    int tid = threadIdx.x, lane = tid & 31, warp = tid >> 5;
    int base = blockIdx.x * 1024 + tid * 4;
    int4 v = make_int4(0, 0, 0, 0);
    if (base + 3 < n) {
        v = *(const int4*)(g_cnt + base);
    } else {
        if (base + 0 < n) v.x = g_cnt[base + 0];
        if (base + 1 < n) v.y = g_cnt[base + 1];
        if (base + 2 < n) v.z = g_cnt[base + 2];
    }
    int s = v.x + v.y + v.z + v.w;
    int t = s;
    #pragma unroll
    for (int o = 1; o < 32; o <<= 1) {
        int u = __shfl_up_sync(0xffffffffu, t, o);
        if (lane >= o) t += u;
    }
    if (lane == 31) wsum[warp] = t;
    __syncthreads();
    if (warp == 0 && lane < 8) {
        int w = wsum[lane];
        #pragma unroll
        for (int o = 1; o < 8; o <<= 1) {
            int u = __shfl_up_sync(0xffu, w, o);
            if (lane >= o) w += u;
        }
        wsum[lane] = w;
    }
    __syncthreads();
    int excl = t - s + (warp ? wsum[warp - 1] : 0);
    int p0 = excl, p1 = p0 + v.x, p2 = p1 + v.y, p3 = p2 + v.z;
    if (base + 3 < n) {
        *(int4*)(g_rowptr + base) = make_int4(p0, p1, p2, p3);
    } else {
        if (base + 0 < n) g_rowptr[base + 0] = p0;
        if (base + 1 < n) g_rowptr[base + 1] = p1;
        if (base + 2 < n) g_rowptr[base + 2] = p2;
    }
    if (tid == 255) g_bsum[blockIdx.x] = excl + s;
}

__global__ void scan2_k(int n, int nb) {
    __shared__ int wsum[4];
    int tid = threadIdx.x, lane = tid & 31, warp = tid >> 5;
    int v = (tid < nb) ? g_bsum[tid] : 0;
    int t = v;
    #pragma unroll
    for (int o = 1; o < 32; o <<= 1) {
        int u = __shfl_up_sync(0xffffffffu, t, o);
        if (lane >= o) t += u;
    }
    if (lane == 31) wsum[warp] = t;
    __syncthreads();
    if (warp == 0 && lane < 4) {
        int w = wsum[lane];
        #pragma unroll
        for (int o = 1; o < 4; o <<= 1) {
            int u = __shfl_up_sync(0xfu, w, o);
            if (lane >= o) w += u;
        }
        wsum[lane] = w;
    }
    __syncthreads();
    int excl = t - v + (warp ? wsum[warp - 1] : 0);
    if (tid < nb) g_boff[tid] = excl;
    if (tid == 127) g_rowptr[n] = wsum[3];
}

__global__ void scan3_k(int n) {
    int i = blockIdx.x * blockDim.x + threadIdx.x;
    if (i < n) {
        int rp = g_rowptr[i] + g_boff[i >> 10];
        g_rowptr[i] = rp;
        g_cursor[i] = rp;
        g_dinv[i] = rsqrtf((float)(g_cnt[i] + 1));
    }
}

__global__ void fill_k(const int* __restrict__ src, const int* __restrict__ dst, int E) {
    int i = blockIdx.x * blockDim.x + threadIdx.x;
    if (i < E) {
        int p = atomicAdd(&g_cursor[dst[i]], 1);
        g_csr[p] = src[i];
    }
}

// ---------------- dense transform: g_h/g_hb = X @ W ----------------
// 128 rows/CTA, 512 threads, 16 warps as 4(col) x 4(row) warp grid.
// Warp covers 32 cols x 32 rows. Thread (lane): cx=lane&3 -> 8 cols, rx=lane>>2
// -> rows {r0+8i}. Per k: 2 LDS.128 W (64B distinct/warp) + 4 LDS.64 X
// (broadcast, conflict-free) + 16 FFMA2. Double-buffered over k.
__global__ __launch_bounds__(512, 1) void gemm8_k(const float* __restrict__ X,
                                                  const float* __restrict__ W, int n) {
    extern __shared__ char sm[];
    ull* sWu = (ull*)sm;                     // [k*64 + c2] col pairs : 64KB
    ull* sXs = (ull*)(sm + 65536);           // [r*XS + k] splatted : 132KB
    int tid = threadIdx.x;
    int row0 = blockIdx.x * 128;

    const float4* W4 = (const float4*)W;
    float4* sW4 = (float4*)sWu;
    for (int i = tid; i < D * 32; i += 512) sW4[i] = W4[i];

    // X fill, vectorized: 128 rows x 32 float4
    for (int i = tid; i < 128 * 32; i += 512) {
        int r = i >> 5, q = i & 31;
        int row = row0 + r;
        float4 v = (row < n) ? ((const float4*)X)[(size_t)row * 32 + q]
                             : make_float4(0.f, 0.f, 0.f, 0.f);
        ull* xp = sXs + r * XS + q * 4;
        xp[0] = pack2(v.x, v.x);
        xp[1] = pack2(v.y, v.y);
        xp[2] = pack2(v.z, v.z);
        xp[3] = pack2(v.w, v.w);
    }
    __syncthreads();

    int lane = tid & 31, wid = tid >> 5;
    int c2base = (wid & 3) * 16 + (lane & 3) * 4;      // col-pair index (x2 = col)
    int r0 = (wid >> 2) * 32 + (lane >> 2);            // rows r0 + 8i
    const ull* wp = sWu + c2base;
    const ull* xp = sXs + r0 * XS;

    ull acc[4][4] = {};          // [row i][col pair j]
    ull wb[2][4], xb[2][4];

    // preload k=0
    lds_v2u64(wb[0][0], wb[0][1], wp);
    lds_v2u64(wb[0][2], wb[0][3], wp + 2);
    #pragma unroll
    for (int i = 0; i < 4; i++) xb[0][i] = lds_u64(xp + i * 8 * XS);

    #pragma unroll 8
    for (int k = 0; k < D; k++) {
        int cur = k & 1, nxt = cur ^ 1;
        if (k < D - 1) {
            const ull* wpn = wp + (k + 1) * 64;
            lds_v2u64(wb[nxt][0], wb[nxt][1], wpn);
            lds_v2u64(wb[nxt][2], wb[nxt][3], wpn + 2);
            #pragma unroll
            for (int i = 0; i < 4; i++) xb[nxt][i] = lds_u64(xp + i * 8 * XS + k + 1);
        }
        #pragma unroll
        for (int i = 0; i < 4; i++) {
            ull xv = xb[cur][i];
            ffma2(acc[i][0], xv, wb[cur][0]);
            ffma2(acc[i][1], xv, wb[cur][1]);
            ffma2(acc[i][2], xv, wb[cur][2]);
            ffma2(acc[i][3], xv, wb[cur][3]);
        }
    }

    #pragma unroll
    for (int i = 0; i < 4; i++) {
        int row = row0 + r0 + 8 * i;
        if (row < n) {
            ull* hp = (ull*)(g_h + (size_t)row * D);
            uint* hb = g_hb + (size_t)row * 64;
            #pragma unroll
            for (int j = 0; j < 4; j++) {
                hp[c2base + j] = acc[i][j];
                float a, b;
                unpack2(acc[i][j], a, b);
                __nv_bfloat162 p = __floats2bfloat162_rn(a, b);
                hb[c2base + j] = *(uint*)&p;
            }
        }
    }
}

// ---------------- aggregation: out = relu(agg + h), warp per node ----------------
__global__ void agg_k(float4* __restrict__ out, int n) {
    int t = blockIdx.x * blockDim.x + threadIdx.x;
    int node = t >> 5;
    int lane = t & 31;
    if (node >= n) return;

    const float4* h4 = (const float4*)g_h;
    const uint2*  hb = (const uint2*)g_hb;
    float dv = g_dinv[node];
    float4 hv = h4[(size_t)node * 32 + lane];
    float ws = dv * dv;
    float4 acc = make_float4(ws * hv.x, ws * hv.y, ws * hv.z, ws * hv.w);

    int s = g_rowptr[node], e = g_rowptr[node + 1];
    int i = s;
    for (; i + 3 < e; i += 4) {
        int u0 = g_csr[i], u1 = g_csr[i + 1], u2 = g_csr[i + 2], u3 = g_csr[i + 3];
        float w0 = g_dinv[u0] * dv, w1 = g_dinv[u1] * dv;
        float w2 = g_dinv[u2] * dv, w3 = g_dinv[u3] * dv;
        uint2 v0 = hb[(size_t)u0 * 32 + lane];
        uint2 v1 = hb[(size_t)u1 * 32 + lane];
        uint2 v2 = hb[(size_t)u2 * 32 + lane];
        uint2 v3 = hb[(size_t)u3 * 32 + lane];
        float a, b;
        bf2x(v0.x, a, b); acc.x += w0 * a; acc.y += w0 * b;
        bf2x(v0.y, a, b); acc.z += w0 * a; acc.w += w0 * b;
        bf2x(v1.x, a, b); acc.x += w1 * a; acc.y += w1 * b;
        bf2x(v1.y, a, b); acc.z += w1 * a; acc.w += w1 * b;
        bf2x(v2.x, a, b); acc.x += w2 * a; acc.y += w2 * b;
        bf2x(v2.y, a, b); acc.z += w2 * a; acc.w += w2 * b;
        bf2x(v3.x, a, b); acc.x += w3 * a; acc.y += w3 * b;
        bf2x(v3.y, a, b); acc.z += w3 * a; acc.w += w3 * b;
    }
    for (; i < e; i++) {
        int u = g_csr[i];
        float w = g_dinv[u] * dv;
        uint2 v = hb[(size_t)u * 32 + lane];
        float a, b;
        bf2x(v.x, a, b); acc.x += w * a; acc.y += w * b;
        bf2x(v.y, a, b); acc.z += w * a; acc.w += w * b;
    }

    out[(size_t)node * 32 + lane] = make_float4(
        fmaxf(acc.x + hv.x, 0.f), fmaxf(acc.y + hv.y, 0.f),
        fmaxf(acc.z + hv.z, 0.f), fmaxf(acc.w + hv.w, 0.f));
}

// ---------------- seed gather: warp per seed ----------------
__global__ void gather_k(const int* __restrict__ seeds, const float4* __restrict__ ent,
                         float4* __restrict__ out, int ns) {
    int t = blockIdx.x * blockDim.x + threadIdx.x;
    int s = t >> 5;
    int lane = t & 31;
    if (s < ns) out[(size_t)s * 32 + lane] = ent[(size_t)seeds[s] * 32 + lane];
}

// ---------------- launch ----------------
extern "C" void kernel_launch(void* const* d_in, const int* in_sizes, int n_in,
                              void* d_out, int out_size) {
    const int*   seeds_sr = (const int*)d_in[0];
    const int*   seeds_tg = (const int*)d_in[1];
    const int*   edges_sr = (const int*)d_in[2];
    const int*   edges_tg = (const int*)d_in[3];
    const float* emb_sr   = (const float*)d_in[4];
    const float* emb_tg   = (const float*)d_in[5];
    const float* W0       = (const float*)d_in[6];
    const float* W1       = (const float*)d_in[7];

    int S = in_sizes[0];
    int E = in_sizes[2] / 2;
    int N = in_sizes[4] / D;

    float* out     = (float*)d_out;
    float* sr_seed = out;
    float* tg_seed = sr_seed + (size_t)S * D;
    float* sr_ent  = tg_seed + (size_t)S * D;
    float* tg_ent  = sr_ent  + (size_t)N * D;

    void* xaddr = nullptr;
    cudaGetSymbolAddress(&xaddr, g_x);

    int smem = 65536 + 128 * XS * 8;   // 64KB W + 132KB X-splat = 196.6KB
    cudaFuncSetAttribute(gemm8_k, cudaFuncAttributeMaxDynamicSharedMemorySize, smem);

    int nb = (N + 1023) / 1024;
    int gtiles = (N + 127) / 128;

    for (int g = 0; g < 2; g++) {
        const int*   edges = g ? edges_tg : edges_sr;
        const float* emb   = g ? emb_tg   : emb_sr;
        const int*   seeds = g ? seeds_tg : seeds_sr;
        float* ent      = g ? tg_ent  : sr_ent;
        float* seed_out = g ? tg_seed : sr_seed;
        const int* src = edges;
        const int* dst = edges + E;

        zero_cnt_k<<<(N + 255) / 256, 256>>>(N);
        count_k<<<(E + 255) / 256, 256>>>(dst, E);
        scan1_k<<<nb, 256>>>(N);
        gemm8_k<<<gtiles, 512, smem>>>(emb, W0, N);   // layer-1 dense (profiled idx 3)
        scan2_k<<<1, 128>>>(N, nb);
        scan3_k<<<(N + 255) / 256, 256>>>(N);
        fill_k<<<(E + 255) / 256, 256>>>(src, dst, E);

        agg_k<<<((size_t)N * 32 + 255) / 256, 256>>>((float4*)xaddr, N);

        gemm8_k<<<gtiles, 512, smem>>>((const float*)xaddr, W1, N);
        agg_k<<<((size_t)N * 32 + 255) / 256, 256>>>((float4*)ent, N);

        gather_k<<<((size_t)S * 32 + 255) / 256, 256>>>(seeds, (const float4*)ent,
                                                        (float4*)seed_out, S);
    }
}

// round 15
// speedup vs baseline: 1.1501x; 1.1501x over previous
#include <cuda_runtime.h>
#include <cuda_bf16.h>

#define D 128
#define MAXN 100000
#define MAXE 1600000
#define XS 129      // padded ull row stride for X-splat (bank de-conflict)
#define RPSTRIDE (MAXN + 4)   // rowptr per-graph stride, 16B-aligned (MAXN+4 divisible by 4)

typedef unsigned long long ull;
typedef unsigned int uint;

// ---------------- device scratch, duplicated per graph (no allocations) ----------------
__device__ int   g_cnt[2][MAXN];
__device__ int   g_rowptr[2][RPSTRIDE];
__device__ int   g_cursor[2][MAXN];
__device__ int   g_csr[2][MAXE];
__device__ float g_dinv[2][MAXN];
__device__ int   g_bsum[2][128];
__device__ int   g_boff[2][128];
__device__ float g_h[2][(size_t)MAXN * D];          // dense output, fp32
__device__ uint  g_hb[2][(size_t)MAXN * (D / 2)];   // dense output, packed bf16x2
__device__ float g_x[2][(size_t)MAXN * D];          // layer-1 activation

// ---------------- packed f32x2 helpers ----------------
__device__ __forceinline__ ull pack2(float x, float y) {
    ull r;
    asm("mov.b64 %0, {%1, %2};" : "=l"(r) : "f"(x), "f"(y));
    return r;
}
__device__ __forceinline__ void unpack2(ull v, float& x, float& y) {
    asm("mov.b64 {%0, %1}, %2;" : "=f"(x), "=f"(y) : "l"(v));
}
__device__ __forceinline__ void ffma2(ull& acc, ull a, ull b) {
    asm("fma.rn.f32x2 %0, %1, %2, %0;" : "+l"(acc) : "l"(a), "l"(b));
}
__device__ __forceinline__ void bf2x(uint v, float& lo, float& hi) {
    lo = __uint_as_float(v << 16);
    hi = __uint_as_float(v & 0xffff0000u);
}
__device__ __forceinline__ void lds_v2u64(ull& a, ull& b, const void* p) {
    asm volatile("ld.shared.v2.u64 {%0, %1}, [%2];" : "=l"(a), "=l"(b) : "l"(__cvta_generic_to_shared(p)));
}

// ---------------- CSR build ----------------
__global__ void zero_cnt_k(int* __restrict__ cnt, int n) {
    int i = blockIdx.x * blockDim.x + threadIdx.x;
    if (i < n) cnt[i] = 0;
}

__global__ void count_k(const int* __restrict__ dst, int* __restrict__ cnt, int E) {
    int i = blockIdx.x * blockDim.x + threadIdx.x;
    if (i < E) atomicAdd(&cnt[dst[i]], 1);
}

__global__ void scan1_k(const int* __restrict__ cnt, int* __restrict__ rowptr,
                        int* __restrict__ bsum, int n) {
    __shared__ int wsum[8];
    int tid = threadIdx.x, lane = tid & 31, warp = tid >> 5;
    int base = blockIdx.x * 1024 + tid * 4;
    int4 v = make_int4(0, 0, 0, 0);
    if (base + 3 < n) {
        v = *(const int4*)(cnt + base);
    } else {
        if (base + 0 < n) v.x = cnt[base + 0];
        if (base + 1 < n) v.y = cnt[base + 1];
        if (base + 2 < n) v.z = cnt[base + 2];
    }
    int s = v.x + v.y + v.z + v.w;
    int t = s;
    #pragma unroll
    for (int o = 1; o < 32; o <<= 1) {
        int u = __shfl_up_sync(0xffffffffu, t, o);
        if (lane >= o) t += u;
    }
    if (lane == 31) wsum[warp] = t;
    __syncthreads();
    if (warp == 0 && lane < 8) {
        int w = wsum[lane];
        #pragma unroll
        for (int o = 1; o < 8; o <<= 1) {
            int u = __shfl_up_sync(0xffu, w, o);
            if (lane >= o) w += u;
        }
        wsum[lane] = w;
    }
    __syncthreads();
    int excl = t - s + (warp ? wsum[warp - 1] : 0);
    int p0 = excl, p1 = p0 + v.x, p2 = p1 + v.y, p3 = p2 + v.z;
    if (base + 3 < n) {
        *(int4*)(rowptr + base) = make_int4(p0, p1, p2, p3);
    } else {
        if (base + 0 < n) rowptr[base + 0] = p0;
        if (base + 1 < n) rowptr[base + 1] = p1;
        if (base + 2 < n) rowptr[base + 2] = p2;
    }
    if (tid == 255) bsum[blockIdx.x] = excl + s;
}

__global__ void scan2_k(const int* __restrict__ bsum, int* __restrict__ boff,
                        int* __restrict__ rowptr, int n, int nb) {
    __shared__ int wsum[4];
    int tid = threadIdx.x, lane = tid & 31, warp = tid >> 5;
    int v = (tid < nb) ? bsum[tid] : 0;
    int t = v;
    #pragma unroll
    for (int o = 1; o < 32; o <<= 1) {
        int u = __shfl_up_sync(0xffffffffu, t, o);
        if (lane >= o) t += u;
    }
    if (lane == 31) wsum[warp] = t;
    __syncthreads();
    if (warp == 0 && lane < 4) {
        int w = wsum[lane];
        #pragma unroll
        for (int o = 1; o < 4; o <<= 1) {
            int u = __shfl_up_sync(0xfu, w, o);
            if (lane >= o) w += u;
        }
        wsum[lane] = w;
    }
    __syncthreads();
    int excl = t - v + (warp ? wsum[warp - 1] : 0);
    if (tid < nb) boff[tid] = excl;
    if (tid == 127) rowptr[n] = wsum[3];
}

__global__ void scan3_k(const int* __restrict__ cnt, const int* __restrict__ boff,
                        int* __restrict__ rowptr, int* __restrict__ cursor,
                        float* __restrict__ dinv, int n) {
    int i = blockIdx.x * blockDim.x + threadIdx.x;
    if (i < n) {
        int rp = rowptr[i] + boff[i >> 10];
        rowptr[i] = rp;
        cursor[i] = rp;
        dinv[i] = rsqrtf((float)(cnt[i] + 1));
    }
}

__global__ void fill_k(const int* __restrict__ src, const int* __restrict__ dst,
                       int* __restrict__ cursor, int* __restrict__ csr, int E) {
    int i = blockIdx.x * blockDim.x + threadIdx.x;
    if (i < E) {
        int p = atomicAdd(&cursor[dst[i]], 1);
        csr[p] = src[i];
    }
}

// ---------------- dense transform (R10 body): h/hb = X @ W ----------------
__global__ __launch_bounds__(512, 1) void gemm8_k(const float* __restrict__ X,
                                                  const float* __restrict__ W,
                                                  float* __restrict__ h,
                                                  uint* __restrict__ hbuf, int n) {
    extern __shared__ char sm[];
    float4* sW4 = (float4*)sm;               // [k*32 + c4] : 64KB
    ull*    sXs = (ull*)(sm + 65536);        // [r*XS + k] splatted : 132KB
    int tid = threadIdx.x;
    int row0 = blockIdx.x * 128;

    const float4* W4 = (const float4*)W;
    for (int i = tid; i < D * 32; i += 512) sW4[i] = W4[i];

    for (int i = tid; i < 128 * D; i += 512) {
        int r = i >> 7, k = i & 127;
        int row = row0 + r;
        float v = (row < n) ? X[(size_t)row * D + k] : 0.f;
        sXs[r * XS + k] = pack2(v, v);
    }
    __syncthreads();

    int lane = tid & 31, wid = tid >> 5;
    int tx = lane & 15;
    int ty = wid * 2 + (lane >> 4);          // 0..31
    const ull* xb = sXs + (ty * 4) * XS;

    ull acc[4][4] = {};

    #pragma unroll 4
    for (int k = 0; k < D; k++) {
        ull w0a, w0b, w1a, w1b;
        lds_v2u64(w0a, w0b, sW4 + k * 32 + tx);
        lds_v2u64(w1a, w1b, sW4 + k * 32 + 16 + tx);
        #pragma unroll
        for (int i = 0; i < 4; i++) {
            ull xv = xb[i * XS + k];
            ffma2(acc[i][0], xv, w0a);
            ffma2(acc[i][1], xv, w0b);
            ffma2(acc[i][2], xv, w1a);
            ffma2(acc[i][3], xv, w1b);
        }
    }

    #pragma unroll
    for (int i = 0; i < 4; i++) {
        int row = row0 + ty * 4 + i;
        if (row < n) {
            ull* hp = (ull*)(h + (size_t)row * D);
            hp[2 * tx]          = acc[i][0];
            hp[2 * tx + 1]      = acc[i][1];
            hp[32 + 2 * tx]     = acc[i][2];
            hp[32 + 2 * tx + 1] = acc[i][3];
            float a, b, c, d2;
            uint2* hb = (uint2*)(hbuf + (size_t)row * 64);
            unpack2(acc[i][0], a, b);
            unpack2(acc[i][1], c, d2);
            __nv_bfloat162 p0 = __floats2bfloat162_rn(a, b);
            __nv_bfloat162 p1 = __floats2bfloat162_rn(c, d2);
            hb[tx] = make_uint2(*(uint*)&p0, *(uint*)&p1);
            unpack2(acc[i][2], a, b);
            unpack2(acc[i][3], c, d2);
            __nv_bfloat162 p2 = __floats2bfloat162_rn(a, b);
            __nv_bfloat162 p3 = __floats2bfloat162_rn(c, d2);
            hb[16 + tx] = make_uint2(*(uint*)&p2, *(uint*)&p3);
        }
    }
}

// ---------------- aggregation: out = relu(agg + h), warp per node ----------------
__global__ void agg_k(float4* __restrict__ out, const float* __restrict__ h,
                      const uint* __restrict__ hbuf, const int* __restrict__ rowptr,
                      const int* __restrict__ csr, const float* __restrict__ dinv, int n) {
    int t = blockIdx.x * blockDim.x + threadIdx.x;
    int node = t >> 5;
    int lane = t & 31;
    if (node >= n) return;

    const float4* h4 = (const float4*)h;
    const uint2*  hb = (const uint2*)hbuf;
    float dv = dinv[node];
    float4 hv = h4[(size_t)node * 32 + lane];
    float ws = dv * dv;
    float4 acc = make_float4(ws * hv.x, ws * hv.y, ws * hv.z, ws * hv.w);

    int s = rowptr[node], e = rowptr[node + 1];
    int i = s;
    for (; i + 3 < e; i += 4) {
        int u0 = csr[i], u1 = csr[i + 1], u2 = csr[i + 2], u3 = csr[i + 3];
        float w0 = dinv[u0] * dv, w1 = dinv[u1] * dv;
        float w2 = dinv[u2] * dv, w3 = dinv[u3] * dv;
        uint2 v0 = hb[(size_t)u0 * 32 + lane];
        uint2 v1 = hb[(size_t)u1 * 32 + lane];
        uint2 v2 = hb[(size_t)u2 * 32 + lane];
        uint2 v3 = hb[(size_t)u3 * 32 + lane];
        float a, b;
        bf2x(v0.x, a, b); acc.x += w0 * a; acc.y += w0 * b;
        bf2x(v0.y, a, b); acc.z += w0 * a; acc.w += w0 * b;
        bf2x(v1.x, a, b); acc.x += w1 * a; acc.y += w1 * b;
        bf2x(v1.y, a, b); acc.z += w1 * a; acc.w += w1 * b;
        bf2x(v2.x, a, b); acc.x += w2 * a; acc.y += w2 * b;
        bf2x(v2.y, a, b); acc.z += w2 * a; acc.w += w2 * b;
        bf2x(v3.x, a, b); acc.x += w3 * a; acc.y += w3 * b;
        bf2x(v3.y, a, b); acc.z += w3 * a; acc.w += w3 * b;
    }
    for (; i < e; i++) {
        int u = csr[i];
        float w = dinv[u] * dv;
        uint2 v = hb[(size_t)u * 32 + lane];
        float a, b;
        bf2x(v.x, a, b); acc.x += w * a; acc.y += w * b;
        bf2x(v.y, a, b); acc.z += w * a; acc.w += w * b;
    }

    out[(size_t)node * 32 + lane] = make_float4(
        fmaxf(acc.x + hv.x, 0.f), fmaxf(acc.y + hv.y, 0.f),
        fmaxf(acc.z + hv.z, 0.f), fmaxf(acc.w + hv.w, 0.f));
}

// ---------------- seed gather: warp per seed ----------------
__global__ void gather_k(const int* __restrict__ seeds, const float4* __restrict__ ent,
                         float4* __restrict__ out, int ns) {
    int t = blockIdx.x * blockDim.x + threadIdx.x;
    int s = t >> 5;
    int lane = t & 31;
    if (s < ns) out[(size_t)s * 32 + lane] = ent[(size_t)seeds[s] * 32 + lane];
}

// ---------------- launch ----------------
static void launch_graph(cudaStream_t st, int g,
                         const int* seeds, const int* edges,
                         const float* emb, const float* W0, const float* W1,
                         float* ent, float* seed_out,
                         int N, int E, int S, int smem) {
    int* cnt;    cudaGetSymbolAddress((void**)&cnt, g_cnt);
    int* rowptr; cudaGetSymbolAddress((void**)&rowptr, g_rowptr);
    int* cursor; cudaGetSymbolAddress((void**)&cursor, g_cursor);
    int* csr;    cudaGetSymbolAddress((void**)&csr, g_csr);
    float* dinv; cudaGetSymbolAddress((void**)&dinv, g_dinv);
    int* bsum;   cudaGetSymbolAddress((void**)&bsum, g_bsum);
    int* boff;   cudaGetSymbolAddress((void**)&boff, g_boff);
    float* h;    cudaGetSymbolAddress((void**)&h, g_h);
    uint* hb;    cudaGetSymbolAddress((void**)&hb, g_hb);
    float* x;    cudaGetSymbolAddress((void**)&x, g_x);
    cnt    += (size_t)g * MAXN;
    rowptr += (size_t)g * RPSTRIDE;
    cursor += (size_t)g * MAXN;
    csr    += (size_t)g * MAXE;
    dinv   += (size_t)g * MAXN;
    bsum   += (size_t)g * 128;
    boff   += (size_t)g * 128;
    h      += (size_t)g * MAXN * D;
    hb     += (size_t)g * MAXN * (D / 2);
    x      += (size_t)g * MAXN * D;

    const int* src = edges;
    const int* dst = edges + E;
    int nb = (N + 1023) / 1024;
    int gtiles = (N + 127) / 128;

    zero_cnt_k<<<(N + 255) / 256, 256, 0, st>>>(cnt, N);
    count_k<<<(E + 255) / 256, 256, 0, st>>>(dst, cnt, E);
    scan1_k<<<nb, 256, 0, st>>>(cnt, rowptr, bsum, N);
    gemm8_k<<<gtiles, 512, smem, st>>>(emb, W0, h, hb, N);
    scan2_k<<<1, 128, 0, st>>>(bsum, boff, rowptr, N, nb);
    scan3_k<<<(N + 255) / 256, 256, 0, st>>>(cnt, boff, rowptr, cursor, dinv, N);
    fill_k<<<(E + 255) / 256, 256, 0, st>>>(src, dst, cursor, csr, E);

    agg_k<<<((size_t)N * 32 + 255) / 256, 256, 0, st>>>((float4*)x, h, hb, rowptr, csr, dinv, N);
    gemm8_k<<<gtiles, 512, smem, st>>>(x, W1, h, hb, N);
    agg_k<<<((size_t)N * 32 + 255) / 256, 256, 0, st>>>((float4*)ent, h, hb, rowptr, csr, dinv, N);
    gather_k<<<((size_t)S * 32 + 255) / 256, 256, 0, st>>>(seeds, (const float4*)ent,
                                                           (float4*)seed_out, S);
}

extern "C" void kernel_launch(void* const* d_in, const int* in_sizes, int n_in,
                              void* d_out, int out_size) {
    const int*   seeds_sr = (const int*)d_in[0];
    const int*   seeds_tg = (const int*)d_in[1];
    const int*   edges_sr = (const int*)d_in[2];
    const int*   edges_tg = (const int*)d_in[3];
    const float* emb_sr   = (const float*)d_in[4];
    const float* emb_tg   = (const float*)d_in[5];
    const float* W0       = (const float*)d_in[6];
    const float* W1       = (const float*)d_in[7];

    int S = in_sizes[0];
    int E = in_sizes[2] / 2;
    int N = in_sizes[4] / D;

    float* out     = (float*)d_out;
    float* sr_seed = out;
    float* tg_seed = sr_seed + (size_t)S * D;
    float* sr_ent  = tg_seed + (size_t)S * D;
    float* tg_ent  = sr_ent  + (size_t)N * D;

    int smem = 65536 + 128 * XS * 8;   // 196.6KB
    static bool inited = false;
    static cudaStream_t s1;
    static cudaEvent_t evFork, evJoin;
    if (!inited) {
        cudaFuncSetAttribute(gemm8_k, cudaFuncAttributeMaxDynamicSharedMemorySize, smem);
        cudaStreamCreateWithFlags(&s1, cudaStreamNonBlocking);
        cudaEventCreateWithFlags(&evFork, cudaEventDisableTiming);
        cudaEventCreateWithFlags(&evJoin, cudaEventDisableTiming);
        inited = true;
    }

    // fork: tg pipeline on side stream, sr pipeline on capture (default) stream
    cudaEventRecord(evFork, 0);
    cudaStreamWaitEvent(s1, evFork, 0);

    launch_graph(0, 0, seeds_sr, edges_sr, emb_sr, W0, W1, sr_ent, sr_seed, N, E, S, smem);
    launch_graph(s1, 1, seeds_tg, edges_tg, emb_tg, W0, W1, tg_ent, tg_seed, N, E, S, smem);

    // join
    cudaEventRecord(evJoin, s1);
    cudaStreamWaitEvent(0, evJoin, 0);
}

// round 16
// speedup vs baseline: 1.3016x; 1.1317x over previous
#include <cuda_runtime.h>
#include <cuda_bf16.h>

#define D 128
#define MAXN 100000
#define MAXE 1600000
#define RPSTRIDE (MAXN + 4)   // rowptr per-graph stride, 16B-aligned
#define XSP 130               // float row stride for X tile (keeps k-even offsets 8B-aligned)

typedef unsigned long long ull;
typedef unsigned int uint;

// ---------------- device scratch, duplicated per graph (no allocations) ----------------
__device__ int   g_cnt[2][MAXN];
__device__ int   g_rowptr[2][RPSTRIDE];
__device__ int   g_cursor[2][MAXN];
__device__ int   g_csr[2][MAXE];
__device__ float g_dinv[2][MAXN];
__device__ int   g_bsum[2][128];
__device__ int   g_boff[2][128];
__device__ float g_h[2][(size_t)MAXN * D];          // dense output, fp32
__device__ uint  g_hb[2][(size_t)MAXN * (D / 2)];   // dense output, packed bf16x2
__device__ float g_x[2][(size_t)MAXN * D];          // layer-1 activation

// ---------------- packed f32x2 helpers ----------------
__device__ __forceinline__ ull pack2(float x, float y) {
    ull r;
    asm("mov.b64 %0, {%1, %2};" : "=l"(r) : "f"(x), "f"(y));
    return r;
}
__device__ __forceinline__ void unpack2(ull v, float& x, float& y) {
    asm("mov.b64 {%0, %1}, %2;" : "=f"(x), "=f"(y) : "l"(v));
}
__device__ __forceinline__ void ffma2(ull& acc, ull a, ull b) {
    asm("fma.rn.f32x2 %0, %1, %2, %0;" : "+l"(acc) : "l"(a), "l"(b));
}
__device__ __forceinline__ void bf2x(uint v, float& lo, float& hi) {
    lo = __uint_as_float(v << 16);
    hi = __uint_as_float(v & 0xffff0000u);
}
__device__ __forceinline__ void lds_v2u64(ull& a, ull& b, const void* p) {
    asm volatile("ld.shared.v2.u64 {%0, %1}, [%2];" : "=l"(a), "=l"(b) : "l"(__cvta_generic_to_shared(p)));
}
__device__ __forceinline__ void lds_f2(float& a, float& b, const void* p) {
    asm volatile("ld.shared.v2.f32 {%0, %1}, [%2];" : "=f"(a), "=f"(b) : "l"(__cvta_generic_to_shared(p)));
}

// ---------------- CSR build ----------------
__global__ void zero_cnt_k(int* __restrict__ cnt, int n) {
    int i = blockIdx.x * blockDim.x + threadIdx.x;
    if (i < n) cnt[i] = 0;
}

__global__ void count_k(const int* __restrict__ dst, int* __restrict__ cnt, int E) {
    int i = blockIdx.x * blockDim.x + threadIdx.x;
    if (i < E) atomicAdd(&cnt[dst[i]], 1);
}

__global__ void scan1_k(const int* __restrict__ cnt, int* __restrict__ rowptr,
                        int* __restrict__ bsum, int n) {
    __shared__ int wsum[8];
    int tid = threadIdx.x, lane = tid & 31, warp = tid >> 5;
    int base = blockIdx.x * 1024 + tid * 4;
    int4 v = make_int4(0, 0, 0, 0);
    if (base + 3 < n) {
        v = *(const int4*)(cnt + base);
    } else {
        if (base + 0 < n) v.x = cnt[base + 0];
        if (base + 1 < n) v.y = cnt[base + 1];
        if (base + 2 < n) v.z = cnt[base + 2];
    }
    int s = v.x + v.y + v.z + v.w;
    int t = s;
    #pragma unroll
    for (int o = 1; o < 32; o <<= 1) {
        int u = __shfl_up_sync(0xffffffffu, t, o);
        if (lane >= o) t += u;
    }
    if (lane == 31) wsum[warp] = t;
    __syncthreads();
    if (warp == 0 && lane < 8) {
        int w = wsum[lane];
        #pragma unroll
        for (int o = 1; o < 8; o <<= 1) {
            int u = __shfl_up_sync(0xffu, w, o);
            if (lane >= o) w += u;
        }
        wsum[lane] = w;
    }
    __syncthreads();
    int excl = t - s + (warp ? wsum[warp - 1] : 0);
    int p0 = excl, p1 = p0 + v.x, p2 = p1 + v.y, p3 = p2 + v.z;
    if (base + 3 < n) {
        *(int4*)(rowptr + base) = make_int4(p0, p1, p2, p3);
    } else {
        if (base + 0 < n) rowptr[base + 0] = p0;
        if (base + 1 < n) rowptr[base + 1] = p1;
        if (base + 2 < n) rowptr[base + 2] = p2;
    }
    if (tid == 255) bsum[blockIdx.x] = excl + s;
}

__global__ void scan2_k(const int* __restrict__ bsum, int* __restrict__ boff,
                        int* __restrict__ rowptr, int n, int nb) {
    __shared__ int wsum[4];
    int tid = threadIdx.x, lane = tid & 31, warp = tid >> 5;
    int v = (tid < nb) ? bsum[tid] : 0;
    int t = v;
    #pragma unroll
    for (int o = 1; o < 32; o <<= 1) {
        int u = __shfl_up_sync(0xffffffffu, t, o);
        if (lane >= o) t += u;
    }
    if (lane == 31) wsum[warp] = t;
    __syncthreads();
    if (warp == 0 && lane < 4) {
        int w = wsum[lane];
        #pragma unroll
        for (int o = 1; o < 4; o <<= 1) {
            int u = __shfl_up_sync(0xfu, w, o);
            if (lane >= o) w += u;
        }
        wsum[lane] = w;
    }
    __syncthreads();
    int excl = t - v + (warp ? wsum[warp - 1] : 0);
    if (tid < nb) boff[tid] = excl;
    if (tid == 127) rowptr[n] = wsum[3];
}

__global__ void scan3_k(const int* __restrict__ cnt, const int* __restrict__ boff,
                        int* __restrict__ rowptr, int* __restrict__ cursor,
                        float* __restrict__ dinv, int n) {
    int i = blockIdx.x * blockDim.x + threadIdx.x;
    if (i < n) {
        int rp = rowptr[i] + boff[i >> 10];
        rowptr[i] = rp;
        cursor[i] = rp;
        dinv[i] = rsqrtf((float)(cnt[i] + 1));
    }
}

__global__ void fill_k(const int* __restrict__ src, const int* __restrict__ dst,
                       int* __restrict__ cursor, int* __restrict__ csr, int E) {
    int i = blockIdx.x * blockDim.x + threadIdx.x;
    if (i < E) {
        int p = atomicAdd(&cursor[dst[i]], 1);
        csr[p] = src[i];
    }
}

// ---------------- dense transform: h/hb = X @ W ----------------
// 64 rows/CTA, 256 threads (8 warps). Warp w: rows w*8..w*8+7 (warp-uniform).
// Lane l: cols 4l..4l+3 (2 ull col-pairs). Per k: ONE LDS.128 fetches W for all
// 128 cols across the warp (zero duplication, 4 wavefronts); X loaded as
// k-pairs via broadcast ld.shared.v2.f32, splat in-register. 96.5KB smem ->
// 2 CTAs/SM: prologue of one CTA overlaps mainloop of the other.
__global__ __launch_bounds__(256, 2) void gemm64_k(const float* __restrict__ X,
                                                   const float* __restrict__ W,
                                                   float* __restrict__ h,
                                                   uint* __restrict__ hbuf, int n) {
    extern __shared__ char sm[];
    float4* sW4 = (float4*)sm;                 // [k*32 + c4] : 64KB
    float*  sX  = (float*)(sm + 65536);        // [r*XSP + k] plain : 33.3KB
    int tid = threadIdx.x;
    int row0 = blockIdx.x * 64;

    const float4* W4 = (const float4*)W;
    for (int i = tid; i < D * 32; i += 256) sW4[i] = W4[i];

    for (int i = tid; i < 64 * 32; i += 256) {
        int r = i >> 5, q = i & 31;
        int row = min(row0 + r, n - 1);
        float4 v = ((const float4*)X)[(size_t)row * 32 + q];
        float* xp = sX + r * XSP + q * 4;
        xp[0] = v.x; xp[1] = v.y; xp[2] = v.z; xp[3] = v.w;
    }
    __syncthreads();

    int lane = tid & 31, wid = tid >> 5;
    const float* xb = sX + (wid * 8) * XSP;

    ull acc[8][2] = {};          // [row r][col pair]

    #pragma unroll 4
    for (int kk = 0; kk < 64; kk++) {
        int k = kk * 2;
        ull wa0, wa1, wb0, wb1;
        lds_v2u64(wa0, wa1, sW4 + k * 32 + lane);          // W row k, cols 4l..4l+3
        lds_v2u64(wb0, wb1, sW4 + (k + 1) * 32 + lane);    // W row k+1
        #pragma unroll
        for (int r = 0; r < 8; r++) {
            float a, b;
            lds_f2(a, b, xb + r * XSP + k);                // X[r][k], X[r][k+1]
            ull xa = pack2(a, a);
            ull xv = pack2(b, b);
            ffma2(acc[r][0], xa, wa0);
            ffma2(acc[r][1], xa, wa1);
            ffma2(acc[r][0], xv, wb0);
            ffma2(acc[r][1], xv, wb1);
        }
    }

    #pragma unroll
    for (int r = 0; r < 8; r++) {
        int row = row0 + wid * 8 + r;
        if (row < n) {
            ull* hp = (ull*)(h + (size_t)row * D);
            hp[2 * lane]     = acc[r][0];
            hp[2 * lane + 1] = acc[r][1];
            float a, b, c, d2;
            unpack2(acc[r][0], a, b);
            unpack2(acc[r][1], c, d2);
            __nv_bfloat162 p0 = __floats2bfloat162_rn(a, b);
            __nv_bfloat162 p1 = __floats2bfloat162_rn(c, d2);
            ((uint2*)(hbuf + (size_t)row * 64))[lane] =
                make_uint2(*(uint*)&p0, *(uint*)&p1);
        }
    }
}

// ---------------- aggregation: out = relu(agg + h), warp per node ----------------
__global__ void agg_k(float4* __restrict__ out, const float* __restrict__ h,
                      const uint* __restrict__ hbuf, const int* __restrict__ rowptr,
                      const int* __restrict__ csr, const float* __restrict__ dinv, int n) {
    int t = blockIdx.x * blockDim.x + threadIdx.x;
    int node = t >> 5;
    int lane = t & 31;
    if (node >= n) return;

    const float4* h4 = (const float4*)h;
    const uint2*  hb = (const uint2*)hbuf;
    float dv = dinv[node];
    float4 hv = h4[(size_t)node * 32 + lane];
    float ws = dv * dv;
    float4 acc = make_float4(ws * hv.x, ws * hv.y, ws * hv.z, ws * hv.w);

    int s = rowptr[node], e = rowptr[node + 1];
    int i = s;
    for (; i + 3 < e; i += 4) {
        int u0 = csr[i], u1 = csr[i + 1], u2 = csr[i + 2], u3 = csr[i + 3];
        float w0 = dinv[u0] * dv, w1 = dinv[u1] * dv;
        float w2 = dinv[u2] * dv, w3 = dinv[u3] * dv;
        uint2 v0 = hb[(size_t)u0 * 32 + lane];
        uint2 v1 = hb[(size_t)u1 * 32 + lane];
        uint2 v2 = hb[(size_t)u2 * 32 + lane];
        uint2 v3 = hb[(size_t)u3 * 32 + lane];
        float a, b;
        bf2x(v0.x, a, b); acc.x += w0 * a; acc.y += w0 * b;
        bf2x(v0.y, a, b); acc.z += w0 * a; acc.w += w0 * b;
        bf2x(v1.x, a, b); acc.x += w1 * a; acc.y += w1 * b;
        bf2x(v1.y, a, b); acc.z += w1 * a; acc.w += w1 * b;
        bf2x(v2.x, a, b); acc.x += w2 * a; acc.y += w2 * b;
        bf2x(v2.y, a, b); acc.z += w2 * a; acc.w += w2 * b;
        bf2x(v3.x, a, b); acc.x += w3 * a; acc.y += w3 * b;
        bf2x(v3.y, a, b); acc.z += w3 * a; acc.w += w3 * b;
    }
    for (; i < e; i++) {
        int u = csr[i];
        float w = dinv[u] * dv;
        uint2 v = hb[(size_t)u * 32 + lane];
        float a, b;
        bf2x(v.x, a, b); acc.x += w * a; acc.y += w * b;
        bf2x(v.y, a, b); acc.z += w * a; acc.w += w * b;
    }

    out[(size_t)node * 32 + lane] = make_float4(
        fmaxf(acc.x + hv.x, 0.f), fmaxf(acc.y + hv.y, 0.f),
        fmaxf(acc.z + hv.z, 0.f), fmaxf(acc.w + hv.w, 0.f));
}

// ---------------- seed gather: warp per seed ----------------
__global__ void gather_k(const int* __restrict__ seeds, const float4* __restrict__ ent,
                         float4* __restrict__ out, int ns) {
    int t = blockIdx.x * blockDim.x + threadIdx.x;
    int s = t >> 5;
    int lane = t & 31;
    if (s < ns) out[(size_t)s * 32 + lane] = ent[(size_t)seeds[s] * 32 + lane];
}

// ---------------- launch ----------------
static void launch_graph(cudaStream_t st, int g,
                         const int* seeds, const int* edges,
                         const float* emb, const float* W0, const float* W1,
                         float* ent, float* seed_out,
                         int N, int E, int S, int smem) {
    int* cnt;    cudaGetSymbolAddress((void**)&cnt, g_cnt);
    int* rowptr; cudaGetSymbolAddress((void**)&rowptr, g_rowptr);
    int* cursor; cudaGetSymbolAddress((void**)&cursor, g_cursor);
    int* csr;    cudaGetSymbolAddress((void**)&csr, g_csr);
    float* dinv; cudaGetSymbolAddress((void**)&dinv, g_dinv);
    int* bsum;   cudaGetSymbolAddress((void**)&bsum, g_bsum);
    int* boff;   cudaGetSymbolAddress((void**)&boff, g_boff);
    float* h;    cudaGetSymbolAddress((void**)&h, g_h);
    uint* hb;    cudaGetSymbolAddress((void**)&hb, g_hb);
    float* x;    cudaGetSymbolAddress((void**)&x, g_x);
    cnt    += (size_t)g * MAXN;
    rowptr += (size_t)g * RPSTRIDE;
    cursor += (size_t)g * MAXN;
    csr    += (size_t)g * MAXE;
    dinv   += (size_t)g * MAXN;
    bsum   += (size_t)g * 128;
    boff   += (size_t)g * 128;
    h      += (size_t)g * MAXN * D;
    hb     += (size_t)g * MAXN * (D / 2);
    x      += (size_t)g * MAXN * D;

    const int* src = edges;
    const int* dst = edges + E;
    int nb = (N + 1023) / 1024;
    int gtiles = (N + 63) / 64;

    zero_cnt_k<<<(N + 255) / 256, 256, 0, st>>>(cnt, N);
    count_k<<<(E + 255) / 256, 256, 0, st>>>(dst, cnt, E);
    scan1_k<<<nb, 256, 0, st>>>(cnt, rowptr, bsum, N);
    gemm64_k<<<gtiles, 256, smem, st>>>(emb, W0, h, hb, N);
    scan2_k<<<1, 128, 0, st>>>(bsum, boff, rowptr, N, nb);
    scan3_k<<<(N + 255) / 256, 256, 0, st>>>(cnt, boff, rowptr, cursor, dinv, N);
    fill_k<<<(E + 255) / 256, 256, 0, st>>>(src, dst, cursor, csr, E);

    agg_k<<<((size_t)N * 32 + 255) / 256, 256, 0, st>>>((float4*)x, h, hb, rowptr, csr, dinv, N);
    gemm64_k<<<gtiles, 256, smem, st>>>(x, W1, h, hb, N);
    agg_k<<<((size_t)N * 32 + 255) / 256, 256, 0, st>>>((float4*)ent, h, hb, rowptr, csr, dinv, N);
    gather_k<<<((size_t)S * 32 + 255) / 256, 256, 0, st>>>(seeds, (const float4*)ent,
                                                           (float4*)seed_out, S);
}

extern "C" void kernel_launch(void* const* d_in, const int* in_sizes, int n_in,
                              void* d_out, int out_size) {
    const int*   seeds_sr = (const int*)d_in[0];
    const int*   seeds_tg = (const int*)d_in[1];
    const int*   edges_sr = (const int*)d_in[2];
    const int*   edges_tg = (const int*)d_in[3];
    const float* emb_sr   = (const float*)d_in[4];
    const float* emb_tg   = (const float*)d_in[5];
    const float* W0       = (const float*)d_in[6];
    const float* W1       = (const float*)d_in[7];

    int S = in_sizes[0];
    int E = in_sizes[2] / 2;
    int N = in_sizes[4] / D;

    float* out     = (float*)d_out;
    float* sr_seed = out;
    float* tg_seed = sr_seed + (size_t)S * D;
    float* sr_ent  = tg_seed + (size_t)S * D;
    float* tg_ent  = sr_ent  + (size_t)N * D;

    int smem = 65536 + 64 * XSP * 4;   // 64KB W + 33.3KB X = 97.8KB -> 2 CTAs/SM
    static bool inited = false;
    static cudaStream_t s1;
    static cudaEvent_t evFork, evJoin;
    if (!inited) {
        cudaFuncSetAttribute(gemm64_k, cudaFuncAttributeMaxDynamicSharedMemorySize, smem);
        cudaStreamCreateWithFlags(&s1, cudaStreamNonBlocking);
        cudaEventCreateWithFlags(&evFork, cudaEventDisableTiming);
        cudaEventCreateWithFlags(&evJoin, cudaEventDisableTiming);
        inited = true;
    }

    // fork: tg pipeline on side stream, sr pipeline on capture (default) stream
    cudaEventRecord(evFork, 0);
    cudaStreamWaitEvent(s1, evFork, 0);

    launch_graph(0, 0, seeds_sr, edges_sr, emb_sr, W0, W1, sr_ent, sr_seed, N, E, S, smem);
    launch_graph(s1, 1, seeds_tg, edges_tg, emb_tg, W0, W1, tg_ent, tg_seed, N, E, S, smem);

    // join
    cudaEventRecord(evJoin, s1);
    cudaStreamWaitEvent(0, evJoin, 0);
}